// round 1
// baseline (speedup 1.0000x reference)
#include <cuda_runtime.h>
#include <cuda_bf16.h>

#define NCOL    4096
#define THREADS 512
#define KITER   16
#define EPS_T   1.1754943508222875e-38f   // float32 tiny

__global__ void __launch_bounds__(THREADS, 2)
subset_op_kernel(const float* __restrict__ scores,
                 const float* __restrict__ gnoise,
                 float* __restrict__ out)
{
    const long long row = blockIdx.x;
    const float4* s4 = reinterpret_cast<const float4*>(scores) + row * (NCOL / 4);
    const float4* g4 = reinterpret_cast<const float4*>(gnoise) + row * (NCOL / 4);
    float4*       o4 = reinterpret_cast<float4*>(out)          + row * (NCOL / 4);

    const int tid  = threadIdx.x;
    const int lane = tid & 31;
    const int warp = tid >> 5;

    __shared__ float red[16];
    __shared__ float bcast;

    // ---- load s0 = scores + g : 8 elements per thread (2 coalesced float4) ----
    float w[8];
    {
        float4 a = s4[tid];
        float4 b = g4[tid];
        w[0] = a.x + b.x; w[1] = a.y + b.y; w[2] = a.z + b.z; w[3] = a.w + b.w;
        a = s4[tid + THREADS];
        b = g4[tid + THREADS];
        w[4] = a.x + b.x; w[5] = a.y + b.y; w[6] = a.z + b.z; w[7] = a.w + b.w;
    }

    // ---- row max (one-time, for stable exp) ----
    float m = w[0];
#pragma unroll
    for (int j = 1; j < 8; j++) m = fmaxf(m, w[j]);
#pragma unroll
    for (int o = 16; o > 0; o >>= 1) m = fmaxf(m, __shfl_xor_sync(0xffffffffu, m, o));
    if (lane == 0) red[warp] = m;
    __syncthreads();
    if (warp == 0) {
        float v = red[lane & 15];
#pragma unroll
        for (int o = 8; o > 0; o >>= 1) v = fmaxf(v, __shfl_xor_sync(0xffffffffu, v, o));
        if (lane == 0) bcast = v;
    }
    __syncthreads();
    const float M = bcast;

    // ---- w = exp(s0 - M) : the ONLY per-element transcendental in the kernel ----
#pragma unroll
    for (int j = 0; j < 8; j++) w[j] = __expf(w[j] - M);

    float kh[8] = {0.f, 0.f, 0.f, 0.f, 0.f, 0.f, 0.f, 0.f};

    // ---- K iterations: softmax via running weights, no log/exp in the loop ----
    for (int it = 0; it < KITER; it++) {
        float p = w[0] + w[1] + w[2] + w[3] + w[4] + w[5] + w[6] + w[7];
#pragma unroll
        for (int o = 16; o > 0; o >>= 1) p += __shfl_xor_sync(0xffffffffu, p, o);
        if (lane == 0) red[warp] = p;
        __syncthreads();
        if (warp == 0) {
            float v = red[lane & 15];
#pragma unroll
            for (int o = 8; o > 0; o >>= 1) v += __shfl_xor_sync(0xffffffffu, v, o);
            if (lane == 0) bcast = __frcp_rn(v);
        }
        __syncthreads();
        const float inv = bcast;
#pragma unroll
        for (int j = 0; j < 8; j++) {
            float oh = w[j] * inv;          // onehot = softmax(s)
            kh[j] += oh;                    // khot accumulate
            w[j]  *= fmaxf(1.0f - oh, EPS_T); // s += log(max(1-onehot,EPS)) in weight space
        }
    }

    // ---- store khot ----
    float4 r;
    r.x = kh[0]; r.y = kh[1]; r.z = kh[2]; r.w = kh[3];
    o4[tid] = r;
    r.x = kh[4]; r.y = kh[5]; r.z = kh[6]; r.w = kh[7];
    o4[tid + THREADS] = r;
}

extern "C" void kernel_launch(void* const* d_in, const int* in_sizes, int n_in,
                              void* d_out, int out_size)
{
    const float* scores = (const float*)d_in[0];
    const float* gnoise = (const float*)d_in[1];
    float* out = (float*)d_out;

    const int total = in_sizes[0];        // 4 * 2048 * 4096
    const int rows  = total / NCOL;       // 8192

    subset_op_kernel<<<rows, THREADS>>>(scores, gnoise, out);
}